// round 13
// baseline (speedup 1.0000x reference)
#include <cuda_runtime.h>

#define B 4
#define V 20000
#define D 64
#define R 64
#define E 640000
#define BD 256            // B*D
#define LN_EPS 1e-5f

#define NV 16             // vertices per chunk
#define SHST 20           // sH row stride (floats)
#define NCHUNK (V / NV)   // 1250
#define GRID_MAIN 592     // 4 blocks per SM (148 SMs), 296 per flavor
#define NBS 80            // scan blocks (80*256 >= V)
#define ECAP 1536         // staged edges per chunk (3x mean degree of 16-vertex chunk)

// Scratch (device globals — zero-initialized at module load; k_main re-zeros
// g_counts behind itself every launch, so hist always starts from zeros)
__device__ float g_relation[R * BD];   // relation[r][b*D+d]
__device__ float g_W1T[64 * 64];       // W1 transposed: [k][d]
__device__ float g_W2T[64 * 64];       // W2 transposed: [k][d]
__device__ int   g_counts[V];
__device__ int   g_starts[V];
__device__ int   g_cursor[V];
__device__ int   g_chunk2[2];          // per-flavor scheduler tickets
__device__ int   g_edata[E];           // (etype<<16) | src, grouped by dst

// ---------------------------------------------------------------------------
// K1: histogram + relation GEMV + weight transposes
__global__ void k_hist_rel(const int* __restrict__ ei,
                           const float* __restrict__ z,
                           const float* __restrict__ Wz,
                           const float* __restrict__ bz,
                           const float* __restrict__ W1,
                           const float* __restrict__ W2) {
    int i = blockIdx.x * blockDim.x + threadIdx.x;
    if (i < E) atomicAdd(&g_counts[ei[3 * i + 2]], 1);
    if (i < R * BD) {
        int r  = i >> 8;
        int bd = i & 255;
        int b  = bd >> 6;
        int d  = bd & 63;
        int row = r * D + d;
        const float* wrow = Wz + row * D;
        const float* zb   = z + b * D;
        float s = __ldg(&bz[row]);
#pragma unroll
        for (int k = 0; k < D; k++) s = fmaf(__ldg(zb + k), __ldg(wrow + k), s);
        g_relation[i] = s;
    }
    if (i < 64 * 64) {   // i = k*64 + d
        g_W1T[i] = __ldg(&W1[(i & 63) * 64 + (i >> 6)]);
        g_W2T[i] = __ldg(&W2[(i & 63) * 64 + (i >> 6)]);
    }
}

// K2: single-pass scan + scheduler ticket reset
__global__ void k_scan() {
    __shared__ int sc[256];
    __shared__ int sRed[8];
    int t = threadIdx.x;
    int bid = blockIdx.x;
    int lane = t & 31;
    int w = t >> 5;
    if (bid == 0 && t < 2) g_chunk2[t] = 0;

    int base = bid * 256;
    int s = 0;
    for (int j = t; j < base; j += 256) s += g_counts[j];
#pragma unroll
    for (int o = 16; o >= 1; o >>= 1) s += __shfl_xor_sync(0xffffffffu, s, o);
    if (lane == 0) sRed[w] = s;

    int i = base + t;
    int c = (i < V) ? g_counts[i] : 0;
    sc[t] = c;
    __syncthreads();
    int pref = sRed[0] + sRed[1] + sRed[2] + sRed[3] +
               sRed[4] + sRed[5] + sRed[6] + sRed[7];
    for (int o = 1; o < 256; o <<= 1) {
        int a = (t >= o) ? sc[t - o] : 0;
        __syncthreads();
        sc[t] += a;
        __syncthreads();
    }
    if (i < V) {
        int st = pref + sc[t] - c;   // global exclusive
        g_starts[i] = st;
        g_cursor[i] = st;
    }
}

// K4: scatter edges into CSR buckets (packed src|etype) — 1 edge/thread
__global__ void k_scatter(const int* __restrict__ ei) {
    int e = blockIdx.x * blockDim.x + threadIdx.x;
    if (e < E) {
        int src = ei[3 * e];
        int et  = ei[3 * e + 1];
        int dst = ei[3 * e + 2];
        int pos = atomicAdd(&g_cursor[dst], 1);
        g_edata[pos] = (et << 16) | src;
    }
}

// ---------------------------------------------------------------------------
// K5: fused aggregation + beta-residual + MLP + LayerNorm + skip.
// b-pair specialization (flavor = blockIdx&1), 4 blocks/SM, NV=16 chunks:
// each epilogue thread owns 8 vertices -> 1 weight LDG feeds 8 FMAs.
// Gather: warp w -> gbl = w&1, quarter = w>>1 (4 vertices each); lane = d-pair
// via float2 LDG.64; unroll 4. NOTE: gather-loop body is codegen-fragile (R8)
// — keep uniform __ldg bounds and self-term load after the edge loop.
__global__ __launch_bounds__(256, 4) void k_main(
    const float* __restrict__ x,
    const float* __restrict__ b1, const float* __restrict__ b2,
    const float* __restrict__ beta,
    const float* __restrict__ lnw, const float* __restrict__ lnb,
    float* __restrict__ out) {

    extern __shared__ float smem[];
    float* sRel = smem;                        // R*128    = 8192 floats (32KB)
    float* sH   = sRel + R * 128;              // 128*SHST = 2560 floats (10KB)
    int*   sE   = (int*)(sH + 128 * SHST);     // ECAP ints (6KB)
    __shared__ float sRS[NV][8];
    __shared__ float sRQ[NV][8];
    __shared__ int sChunk;

    int t = threadIdx.x;
    int w = t >> 5;
    int lane = t & 31;
    int flavor = blockIdx.x & 1;
    int bBase  = flavor << 1;

    // epilogue identity: 8 vertices per thread, octet selected by h
    int bb = t >> 7;           // local b (0/1)
    int h  = (t >> 6) & 1;     // vi octet (0: vi 0-7, 1: vi 8-15)
    int d  = t & 63;
    int b  = bBase + bb;

    // gather identity
    int gbl     = w & 1;       // local b
    int quarter = w >> 1;      // 0..3, 4 vertices each
    int gb      = bBase + gbl;

    // stage relation slice (columns for this b-pair)
    for (int i = t; i < R * 128; i += 256)
        sRel[i] = g_relation[((i >> 7) << 8) + (bBase << 6) + (i & 127)];

    float bb1 = __ldg(b1 + d), bb2 = __ldg(b2 + d);
    float wln = __ldg(lnw + d), bln = __ldg(lnb + d);
    float2 bet2 = ((const float2*)beta)[lane];

    const float2* xb2 = (const float2*)x + (size_t)gb * (V * D / 2) + lane;
    const float*  xres = x + (size_t)b * V * D + d;
    float* sRelB = sRel + (gbl << 6) + 2 * lane;

    for (;;) {
        if (t == 0) sChunk = atomicAdd(&g_chunk2[flavor], 1);
        __syncthreads();               // publishes sChunk; sE/sH safe to overwrite
        int chunk = sChunk;
        if (chunk >= NCHUNK) break;

        int v0 = chunk * NV;
        int eBeg = __ldg(&g_starts[v0]);
        int eEnd = (v0 + NV < V) ? __ldg(&g_starts[v0 + NV]) : E;
        int nE = eEnd - eBeg;

        int nStage = nE < ECAP ? nE : ECAP;
        for (int i = t; i < nStage; i += 256) sE[i] = __ldg(&g_edata[eBeg + i]);
        if (flavor == 0 && t < NV) g_counts[v0 + t] = 0;  // re-zero once
        __syncthreads();

        // ---- gather: each warp handles 4 vertices for its b ----
        for (int q = 0; q < 4; q++) {
            int vi = (quarter << 2) + q;
            int v  = v0 + vi;
            int lo  = __ldg(&g_starts[v]) - eBeg;
            int hi  = ((v + 1 < V) ? __ldg(&g_starts[v + 1]) : E) - eBeg;
            int cnt = hi - lo;
            float acc0 = 0.f, acc1 = 0.f;

            if (hi <= ECAP) {
                const int* ed = sE + lo;
                int j = 0;
                for (; j + 4 <= cnt; j += 4) {
                    int e0 = ed[j],     e1 = ed[j + 1];
                    int e2 = ed[j + 2], e3 = ed[j + 3];
                    float2 x0 = __ldg(xb2 + (e0 & 0xFFFF) * 32);
                    float2 x1 = __ldg(xb2 + (e1 & 0xFFFF) * 32);
                    float2 x2 = __ldg(xb2 + (e2 & 0xFFFF) * 32);
                    float2 x3 = __ldg(xb2 + (e3 & 0xFFFF) * 32);
                    float2 r0 = *(const float2*)(sRelB + ((e0 >> 16) << 7));
                    float2 r1 = *(const float2*)(sRelB + ((e1 >> 16) << 7));
                    float2 r2 = *(const float2*)(sRelB + ((e2 >> 16) << 7));
                    float2 r3 = *(const float2*)(sRelB + ((e3 >> 16) << 7));
                    acc0 = fmaf(r0.x, x0.x, acc0); acc1 = fmaf(r0.y, x0.y, acc1);
                    acc0 = fmaf(r1.x, x1.x, acc0); acc1 = fmaf(r1.y, x1.y, acc1);
                    acc0 = fmaf(r2.x, x2.x, acc0); acc1 = fmaf(r2.y, x2.y, acc1);
                    acc0 = fmaf(r3.x, x3.x, acc0); acc1 = fmaf(r3.y, x3.y, acc1);
                }
                for (; j < cnt; j++) {
                    int e = ed[j];
                    float2 xv = __ldg(xb2 + (e & 0xFFFF) * 32);
                    float2 rv = *(const float2*)(sRelB + ((e >> 16) << 7));
                    acc0 = fmaf(rv.x, xv.x, acc0);
                    acc1 = fmaf(rv.y, xv.y, acc1);
                }
            } else {
                // rare fallback: chunk overflowed staging buffer
                const int* ed = g_edata + eBeg + lo;
                for (int j = 0; j < cnt; j++) {
                    int e = __ldg(ed + j);
                    float2 xv = __ldg(xb2 + (e & 0xFFFF) * 32);
                    float2 rv = *(const float2*)(sRelB + ((e >> 16) << 7));
                    acc0 = fmaf(rv.x, xv.x, acc0);
                    acc1 = fmaf(rv.y, xv.y, acc1);
                }
            }

            float2 xs2 = __ldg(xb2 + (size_t)v * 32);
            int base = ((gbl << 6) + 2 * lane) * SHST + vi;
            sH[base]        = fmaf(bet2.x, xs2.x, acc0);
            sH[base + SHST] = fmaf(bet2.y, xs2.y, acc1);
        }
        __syncthreads();

        // ---- matmul 1: s[j] = relu(h0[h*8+j] @ W1^T + b1) ----
        float s[8];
#pragma unroll
        for (int j = 0; j < 8; j++) s[j] = bb1;
#pragma unroll
        for (int k = 0; k < 64; k++) {
            float wv = __ldg(&g_W1T[(k << 6) + d]);
            const float4* hp = reinterpret_cast<const float4*>(&sH[((bb << 6) + k) * SHST]);
            float4 ha = hp[2 * h], hc = hp[2 * h + 1];
            s[0] = fmaf(ha.x, wv, s[0]); s[1] = fmaf(ha.y, wv, s[1]);
            s[2] = fmaf(ha.z, wv, s[2]); s[3] = fmaf(ha.w, wv, s[3]);
            s[4] = fmaf(hc.x, wv, s[4]); s[5] = fmaf(hc.y, wv, s[5]);
            s[6] = fmaf(hc.z, wv, s[6]); s[7] = fmaf(hc.w, wv, s[7]);
        }
        __syncthreads();
        {
            float4* sHrow = reinterpret_cast<float4*>(&sH[((bb << 6) + d) * SHST]);
            sHrow[2 * h]     = make_float4(fmaxf(s[0], 0.f), fmaxf(s[1], 0.f),
                                           fmaxf(s[2], 0.f), fmaxf(s[3], 0.f));
            sHrow[2 * h + 1] = make_float4(fmaxf(s[4], 0.f), fmaxf(s[5], 0.f),
                                           fmaxf(s[6], 0.f), fmaxf(s[7], 0.f));
        }
        __syncthreads();

        // ---- matmul 2: s[j] = t1[h*8+j] @ W2^T + b2 ----
#pragma unroll
        for (int j = 0; j < 8; j++) s[j] = bb2;
#pragma unroll
        for (int k = 0; k < 64; k++) {
            float wv = __ldg(&g_W2T[(k << 6) + d]);
            const float4* hp = reinterpret_cast<const float4*>(&sH[((bb << 6) + k) * SHST]);
            float4 ha = hp[2 * h], hc = hp[2 * h + 1];
            s[0] = fmaf(ha.x, wv, s[0]); s[1] = fmaf(ha.y, wv, s[1]);
            s[2] = fmaf(ha.z, wv, s[2]); s[3] = fmaf(ha.w, wv, s[3]);
            s[4] = fmaf(hc.x, wv, s[4]); s[5] = fmaf(hc.y, wv, s[5]);
            s[6] = fmaf(hc.z, wv, s[6]); s[7] = fmaf(hc.w, wv, s[7]);
        }

        // ---- LayerNorm (two-pass, warp shuffles + cross-warp combine) ----
        float mu[8];
#pragma unroll
        for (int j = 0; j < 8; j++) {
            float sm = s[j];
#pragma unroll
            for (int o = 16; o >= 1; o >>= 1)
                sm += __shfl_xor_sync(0xffffffffu, sm, o);
            if (lane == 0) sRS[(h << 3) + j][w] = sm;
        }
        __syncthreads();
#pragma unroll
        for (int j = 0; j < 8; j++)
            mu[j] = (sRS[(h << 3) + j][w] + sRS[(h << 3) + j][w ^ 1]) * (1.f / 64.f);
#pragma unroll
        for (int j = 0; j < 8; j++) {
            float hm = s[j] - mu[j];
            float q = hm * hm;
#pragma unroll
            for (int o = 16; o >= 1; o >>= 1)
                q += __shfl_xor_sync(0xffffffffu, q, o);
            if (lane == 0) sRQ[(h << 3) + j][w] = q;
        }
        __syncthreads();

        size_t obase = (size_t)b * V * D + (size_t)(v0 + (h << 3)) * D + d;
#pragma unroll
        for (int j = 0; j < 8; j++) {
            float var = (sRQ[(h << 3) + j][w] + sRQ[(h << 3) + j][w ^ 1]) * (1.f / 64.f);
            float hm  = s[j] - mu[j];
            float xself = __ldg(xres + (size_t)(v0 + (h << 3) + j) * D);
            out[obase + (size_t)j * D] =
                fmaf(hm * rsqrtf(var + LN_EPS), wln, bln) + xself;
        }
    }
}

// ---------------------------------------------------------------------------
extern "C" void kernel_launch(void* const* d_in, const int* in_sizes, int n_in,
                              void* d_out, int out_size) {
    const float* x    = (const float*)d_in[0];
    const float* z    = (const float*)d_in[1];
    const int*   ei   = (const int*)d_in[2];
    // d_in[3] = r_index (unused by the reference)
    const float* Wz   = (const float*)d_in[4];
    const float* bz   = (const float*)d_in[5];
    const float* W1   = (const float*)d_in[6];
    const float* b1   = (const float*)d_in[7];
    const float* W2   = (const float*)d_in[8];
    const float* b2   = (const float*)d_in[9];
    const float* beta = (const float*)d_in[10];
    const float* lnw  = (const float*)d_in[11];
    const float* lnb  = (const float*)d_in[12];
    float* out = (float*)d_out;

    const int SMEM_MAIN = (R * 128 + 128 * SHST) * 4 + ECAP * 4;  // 49152 B
    cudaFuncSetAttribute(k_main, cudaFuncAttributeMaxDynamicSharedMemorySize,
                         SMEM_MAIN);

    k_hist_rel<<<(E + 255) / 256, 256>>>(ei, z, Wz, bz, W1, W2);
    k_scan<<<NBS, 256>>>();
    k_scatter<<<(E + 255) / 256, 256>>>(ei);
    k_main<<<GRID_MAIN, 256, SMEM_MAIN>>>(x, b1, b2, beta, lnw, lnb, out);
}

// round 14
// speedup vs baseline: 1.0915x; 1.0915x over previous
#include <cuda_runtime.h>
#include <cuda_fp16.h>

#define B 4
#define V 20000
#define D 64
#define R 64
#define E 640000
#define BD 256            // B*D
#define LN_EPS 1e-5f

#define NV 16             // vertices per chunk
#define SHST 20           // sH row stride (floats)
#define NCHUNK (V / NV)   // 1250
#define GRID_MAIN 592     // 4 blocks per SM (148 SMs), 296 per flavor
#define NBS 80            // scan blocks (80*256 >= V)
#define ECAP 1536         // staged edges per chunk

// Scratch (device globals — zero-initialized at module load; k_main re-zeros
// g_counts behind itself every launch, so hist always starts from zeros)
__device__ float g_relation[R * BD];   // relation[r][b*D+d], f32 master copy
__device__ float g_W1T[64 * 64];       // W1 transposed: [k][d]
__device__ float g_W2T[64 * 64];       // W2 transposed: [k][d]
__device__ int   g_counts[V];
__device__ int   g_starts[V];
__device__ int   g_cursor[V];
__device__ int   g_chunk2[2];          // per-flavor scheduler tickets
__device__ int   g_edata[E];           // (etype<<22) | src, grouped by dst

// ---------------------------------------------------------------------------
// K1: histogram + relation GEMV + weight transposes
__global__ void k_hist_rel(const int* __restrict__ ei,
                           const float* __restrict__ z,
                           const float* __restrict__ Wz,
                           const float* __restrict__ bz,
                           const float* __restrict__ W1,
                           const float* __restrict__ W2) {
    int i = blockIdx.x * blockDim.x + threadIdx.x;
    if (i < E) atomicAdd(&g_counts[ei[3 * i + 2]], 1);
    if (i < R * BD) {
        int r  = i >> 8;
        int bd = i & 255;
        int b  = bd >> 6;
        int d  = bd & 63;
        int row = r * D + d;
        const float* wrow = Wz + row * D;
        const float* zb   = z + b * D;
        float s = __ldg(&bz[row]);
#pragma unroll
        for (int k = 0; k < D; k++) s = fmaf(__ldg(zb + k), __ldg(wrow + k), s);
        g_relation[i] = s;
    }
    if (i < 64 * 64) {   // i = k*64 + d
        g_W1T[i] = __ldg(&W1[(i & 63) * 64 + (i >> 6)]);
        g_W2T[i] = __ldg(&W2[(i & 63) * 64 + (i >> 6)]);
    }
}

// K2: single-pass scan + scheduler ticket reset
__global__ void k_scan() {
    __shared__ int sc[256];
    __shared__ int sRed[8];
    int t = threadIdx.x;
    int bid = blockIdx.x;
    int lane = t & 31;
    int w = t >> 5;
    if (bid == 0 && t < 2) g_chunk2[t] = 0;

    int base = bid * 256;
    int s = 0;
    for (int j = t; j < base; j += 256) s += g_counts[j];
#pragma unroll
    for (int o = 16; o >= 1; o >>= 1) s += __shfl_xor_sync(0xffffffffu, s, o);
    if (lane == 0) sRed[w] = s;

    int i = base + t;
    int c = (i < V) ? g_counts[i] : 0;
    sc[t] = c;
    __syncthreads();
    int pref = sRed[0] + sRed[1] + sRed[2] + sRed[3] +
               sRed[4] + sRed[5] + sRed[6] + sRed[7];
    for (int o = 1; o < 256; o <<= 1) {
        int a = (t >= o) ? sc[t - o] : 0;
        __syncthreads();
        sc[t] += a;
        __syncthreads();
    }
    if (i < V) {
        int st = pref + sc[t] - c;   // global exclusive
        g_starts[i] = st;
        g_cursor[i] = st;
    }
}

// K4: scatter edges into CSR buckets — 1 edge/thread.
// Pack: (etype << 22) | src  ->  (e >> 16) == etype*64 == half2 rel offset.
__global__ void k_scatter(const int* __restrict__ ei) {
    int e = blockIdx.x * blockDim.x + threadIdx.x;
    if (e < E) {
        int src = ei[3 * e];
        int et  = ei[3 * e + 1];
        int dst = ei[3 * e + 2];
        int pos = atomicAdd(&g_cursor[dst], 1);
        g_edata[pos] = (et << 22) | src;
    }
}

// ---------------------------------------------------------------------------
// K5: fused aggregation + beta-residual + MLP + LayerNorm + skip.
// b-pair specialization (flavor = blockIdx&1), 4 blocks/SM, NV=16 chunks.
// Relation slice staged in smem as fp16 (half2 per lane d-pair): halves the
// relation LDS phases (the binding L1tex term); accumulation stays f32.
// Gather: warp w -> gbl = w&1, quarter = w>>1 (4 vertices each); lane = d-pair
// via float2 LDG.64; unroll 4. NOTE: gather-loop body is codegen-fragile (R8)
// — keep uniform __ldg bounds and self-term load after the edge loop.
__global__ __launch_bounds__(256, 4) void k_main(
    const float* __restrict__ x,
    const float* __restrict__ b1, const float* __restrict__ b2,
    const float* __restrict__ beta,
    const float* __restrict__ lnw, const float* __restrict__ lnb,
    float* __restrict__ out) {

    extern __shared__ float smem[];
    __half2* sRelH = (__half2*)smem;           // R*64 half2 = 16KB
    float* sH = smem + R * 64;                 // 128*SHST = 2560 floats (10KB)
    int*   sE = (int*)(sH + 128 * SHST);       // ECAP ints (6KB)
    __shared__ float sRS[NV][8];
    __shared__ float sRQ[NV][8];
    __shared__ int sChunk;

    int t = threadIdx.x;
    int w = t >> 5;
    int lane = t & 31;
    int flavor = blockIdx.x & 1;
    int bBase  = flavor << 1;

    // epilogue identity: 8 vertices per thread, octet selected by h
    int bb = t >> 7;           // local b (0/1)
    int h  = (t >> 6) & 1;     // vi octet (0: vi 0-7, 1: vi 8-15)
    int d  = t & 63;
    int b  = bBase + bb;

    // gather identity
    int gbl     = w & 1;       // local b
    int quarter = w >> 1;      // 0..3, 4 vertices each
    int gb      = bBase + gbl;

    // stage relation slice as fp16: sRelH[r*64 + c] = half2 of
    // g_relation[r*256 + bBase*64 + 2c .. +1]   (c = gbl*32 + lane)
    for (int i = t; i < R * 64; i += 256) {
        int r = i >> 6, c = i & 63;
        float2 rv = *(const float2*)&g_relation[(r << 8) + (bBase << 6) + 2 * c];
        sRelH[i] = __floats2half2_rn(rv.x, rv.y);
    }

    float bb1 = __ldg(b1 + d), bb2 = __ldg(b2 + d);
    float wln = __ldg(lnw + d), bln = __ldg(lnb + d);
    float2 bet2 = ((const float2*)beta)[lane];

    const float2* xb2 = (const float2*)x + (size_t)gb * (V * D / 2) + lane;
    const float*  xres = x + (size_t)b * V * D + d;
    const __half2* sRelB = sRelH + (gbl << 5) + lane;

    for (;;) {
        if (t == 0) sChunk = atomicAdd(&g_chunk2[flavor], 1);
        __syncthreads();               // publishes sChunk; sE/sH safe to overwrite
        int chunk = sChunk;
        if (chunk >= NCHUNK) break;

        int v0 = chunk * NV;
        int eBeg = __ldg(&g_starts[v0]);
        int eEnd = (v0 + NV < V) ? __ldg(&g_starts[v0 + NV]) : E;
        int nE = eEnd - eBeg;

        int nStage = nE < ECAP ? nE : ECAP;
        for (int i = t; i < nStage; i += 256) sE[i] = __ldg(&g_edata[eBeg + i]);
        if (flavor == 0 && t < NV) g_counts[v0 + t] = 0;  // re-zero once
        __syncthreads();

        // ---- gather: each warp handles 4 vertices for its b ----
        for (int q = 0; q < 4; q++) {
            int vi = (quarter << 2) + q;
            int v  = v0 + vi;
            int lo  = __ldg(&g_starts[v]) - eBeg;
            int hi  = ((v + 1 < V) ? __ldg(&g_starts[v + 1]) : E) - eBeg;
            int cnt = hi - lo;
            float acc0 = 0.f, acc1 = 0.f;

            if (hi <= ECAP) {
                const int* ed = sE + lo;
                int j = 0;
                for (; j + 4 <= cnt; j += 4) {
                    int e0 = ed[j],     e1 = ed[j + 1];
                    int e2 = ed[j + 2], e3 = ed[j + 3];
                    float2 x0 = __ldg(xb2 + (e0 & 0x3FFFFF) * 32);
                    float2 x1 = __ldg(xb2 + (e1 & 0x3FFFFF) * 32);
                    float2 x2 = __ldg(xb2 + (e2 & 0x3FFFFF) * 32);
                    float2 x3 = __ldg(xb2 + (e3 & 0x3FFFFF) * 32);
                    float2 r0 = __half22float2(sRelB[e0 >> 16]);
                    float2 r1 = __half22float2(sRelB[e1 >> 16]);
                    float2 r2 = __half22float2(sRelB[e2 >> 16]);
                    float2 r3 = __half22float2(sRelB[e3 >> 16]);
                    acc0 = fmaf(r0.x, x0.x, acc0); acc1 = fmaf(r0.y, x0.y, acc1);
                    acc0 = fmaf(r1.x, x1.x, acc0); acc1 = fmaf(r1.y, x1.y, acc1);
                    acc0 = fmaf(r2.x, x2.x, acc0); acc1 = fmaf(r2.y, x2.y, acc1);
                    acc0 = fmaf(r3.x, x3.x, acc0); acc1 = fmaf(r3.y, x3.y, acc1);
                }
                for (; j < cnt; j++) {
                    int e = ed[j];
                    float2 xv = __ldg(xb2 + (e & 0x3FFFFF) * 32);
                    float2 rv = __half22float2(sRelB[e >> 16]);
                    acc0 = fmaf(rv.x, xv.x, acc0);
                    acc1 = fmaf(rv.y, xv.y, acc1);
                }
            } else {
                // rare fallback: chunk overflowed staging buffer
                const int* ed = g_edata + eBeg + lo;
                for (int j = 0; j < cnt; j++) {
                    int e = __ldg(ed + j);
                    float2 xv = __ldg(xb2 + (e & 0x3FFFFF) * 32);
                    float2 rv = __half22float2(sRelB[e >> 16]);
                    acc0 = fmaf(rv.x, xv.x, acc0);
                    acc1 = fmaf(rv.y, xv.y, acc1);
                }
            }

            float2 xs2 = __ldg(xb2 + (size_t)v * 32);
            int base = ((gbl << 6) + 2 * lane) * SHST + vi;
            sH[base]        = fmaf(bet2.x, xs2.x, acc0);
            sH[base + SHST] = fmaf(bet2.y, xs2.y, acc1);
        }
        __syncthreads();

        // ---- matmul 1: s[j] = relu(h0[h*8+j] @ W1^T + b1) ----
        float s[8];
#pragma unroll
        for (int j = 0; j < 8; j++) s[j] = bb1;
#pragma unroll
        for (int k = 0; k < 64; k++) {
            float wv = __ldg(&g_W1T[(k << 6) + d]);
            const float4* hp = reinterpret_cast<const float4*>(&sH[((bb << 6) + k) * SHST]);
            float4 ha = hp[2 * h], hc = hp[2 * h + 1];
            s[0] = fmaf(ha.x, wv, s[0]); s[1] = fmaf(ha.y, wv, s[1]);
            s[2] = fmaf(ha.z, wv, s[2]); s[3] = fmaf(ha.w, wv, s[3]);
            s[4] = fmaf(hc.x, wv, s[4]); s[5] = fmaf(hc.y, wv, s[5]);
            s[6] = fmaf(hc.z, wv, s[6]); s[7] = fmaf(hc.w, wv, s[7]);
        }
        __syncthreads();
        {
            float4* sHrow = reinterpret_cast<float4*>(&sH[((bb << 6) + d) * SHST]);
            sHrow[2 * h]     = make_float4(fmaxf(s[0], 0.f), fmaxf(s[1], 0.f),
                                           fmaxf(s[2], 0.f), fmaxf(s[3], 0.f));
            sHrow[2 * h + 1] = make_float4(fmaxf(s[4], 0.f), fmaxf(s[5], 0.f),
                                           fmaxf(s[6], 0.f), fmaxf(s[7], 0.f));
        }
        __syncthreads();

        // ---- matmul 2: s[j] = t1[h*8+j] @ W2^T + b2 ----
#pragma unroll
        for (int j = 0; j < 8; j++) s[j] = bb2;
#pragma unroll
        for (int k = 0; k < 64; k++) {
            float wv = __ldg(&g_W2T[(k << 6) + d]);
            const float4* hp = reinterpret_cast<const float4*>(&sH[((bb << 6) + k) * SHST]);
            float4 ha = hp[2 * h], hc = hp[2 * h + 1];
            s[0] = fmaf(ha.x, wv, s[0]); s[1] = fmaf(ha.y, wv, s[1]);
            s[2] = fmaf(ha.z, wv, s[2]); s[3] = fmaf(ha.w, wv, s[3]);
            s[4] = fmaf(hc.x, wv, s[4]); s[5] = fmaf(hc.y, wv, s[5]);
            s[6] = fmaf(hc.z, wv, s[6]); s[7] = fmaf(hc.w, wv, s[7]);
        }

        // ---- LayerNorm (two-pass, warp shuffles + cross-warp combine) ----
        float mu[8];
#pragma unroll
        for (int j = 0; j < 8; j++) {
            float sm = s[j];
#pragma unroll
            for (int o = 16; o >= 1; o >>= 1)
                sm += __shfl_xor_sync(0xffffffffu, sm, o);
            if (lane == 0) sRS[(h << 3) + j][w] = sm;
        }
        __syncthreads();
#pragma unroll
        for (int j = 0; j < 8; j++)
            mu[j] = (sRS[(h << 3) + j][w] + sRS[(h << 3) + j][w ^ 1]) * (1.f / 64.f);
#pragma unroll
        for (int j = 0; j < 8; j++) {
            float hm = s[j] - mu[j];
            float q = hm * hm;
#pragma unroll
            for (int o = 16; o >= 1; o >>= 1)
                q += __shfl_xor_sync(0xffffffffu, q, o);
            if (lane == 0) sRQ[(h << 3) + j][w] = q;
        }
        __syncthreads();

        size_t obase = (size_t)b * V * D + (size_t)(v0 + (h << 3)) * D + d;
#pragma unroll
        for (int j = 0; j < 8; j++) {
            float var = (sRQ[(h << 3) + j][w] + sRQ[(h << 3) + j][w ^ 1]) * (1.f / 64.f);
            float hm  = s[j] - mu[j];
            float xself = __ldg(xres + (size_t)(v0 + (h << 3) + j) * D);
            out[obase + (size_t)j * D] =
                fmaf(hm * rsqrtf(var + LN_EPS), wln, bln) + xself;
        }
    }
}

// ---------------------------------------------------------------------------
extern "C" void kernel_launch(void* const* d_in, const int* in_sizes, int n_in,
                              void* d_out, int out_size) {
    const float* x    = (const float*)d_in[0];
    const float* z    = (const float*)d_in[1];
    const int*   ei   = (const int*)d_in[2];
    // d_in[3] = r_index (unused by the reference)
    const float* Wz   = (const float*)d_in[4];
    const float* bz   = (const float*)d_in[5];
    const float* W1   = (const float*)d_in[6];
    const float* b1   = (const float*)d_in[7];
    const float* W2   = (const float*)d_in[8];
    const float* b2   = (const float*)d_in[9];
    const float* beta = (const float*)d_in[10];
    const float* lnw  = (const float*)d_in[11];
    const float* lnb  = (const float*)d_in[12];
    float* out = (float*)d_out;

    const int SMEM_MAIN = R * 64 * 4 + 128 * SHST * 4 + ECAP * 4;  // 32768+10240+6144 = 49152... (16KB rel)
    cudaFuncSetAttribute(k_main, cudaFuncAttributeMaxDynamicSharedMemorySize,
                         SMEM_MAIN);

    k_hist_rel<<<(E + 255) / 256, 256>>>(ei, z, Wz, bz, W1, W2);
    k_scan<<<NBS, 256>>>();
    k_scatter<<<(E + 255) / 256, 256>>>(ei);
    k_main<<<GRID_MAIN, 256, SMEM_MAIN>>>(x, b1, b2, beta, lnw, lnb, out);
}

// round 15
// speedup vs baseline: 1.1364x; 1.0412x over previous
#include <cuda_runtime.h>
#include <cuda_fp16.h>

#define B 4
#define V 20000
#define D 64
#define R 64
#define E 640000
#define BD 256            // B*D
#define LN_EPS 1e-5f

#define NV 16             // vertices per chunk
#define SHST 20           // sH row stride (floats)
#define NCHUNK (V / NV)   // 1250
#define GRID_MAIN 592     // 4 blocks per SM (148 SMs), 296 per flavor
#define NBS 80            // scan blocks (80*256 >= V)
#define ECAP 1536         // staged edges per chunk
#define XH_N (B * V * 32) // half2 element count of x (B*V*D/2)

// Scratch (device globals — zero-initialized at module load; k_main re-zeros
// g_counts behind itself every launch, so hist always starts from zeros)
__device__ float   g_relation[R * BD];   // relation[r][b*D+d], f32 master copy
__device__ __half2 g_xh[XH_N];           // fp16 copy of x for the gather
__device__ float   g_W1T[64 * 64];       // W1 transposed: [k][d]
__device__ float   g_W2T[64 * 64];       // W2 transposed: [k][d]
__device__ int     g_counts[V];
__device__ int     g_starts[V];
__device__ int     g_cursor[V];
__device__ int     g_chunk2[2];          // per-flavor scheduler tickets
__device__ int     g_edata[E];           // (etype<<22) | src, grouped by dst

// ---------------------------------------------------------------------------
// K1: histogram + relation GEMV + weight transposes + x -> fp16 conversion
__global__ void k_hist_rel(const int* __restrict__ ei,
                           const float* __restrict__ z,
                           const float* __restrict__ Wz,
                           const float* __restrict__ bz,
                           const float* __restrict__ W1,
                           const float* __restrict__ W2,
                           const float* __restrict__ x) {
    int i = blockIdx.x * blockDim.x + threadIdx.x;
    if (i < E) atomicAdd(&g_counts[ei[3 * i + 2]], 1);
    if (i < R * BD) {
        int r  = i >> 8;
        int bd = i & 255;
        int b  = bd >> 6;
        int d  = bd & 63;
        int row = r * D + d;
        const float* wrow = Wz + row * D;
        const float* zb   = z + b * D;
        float s = __ldg(&bz[row]);
#pragma unroll
        for (int k = 0; k < D; k++) s = fmaf(__ldg(zb + k), __ldg(wrow + k), s);
        g_relation[i] = s;
    }
    if (i < 64 * 64) {   // i = k*64 + d
        g_W1T[i] = __ldg(&W1[(i & 63) * 64 + (i >> 6)]);
        g_W2T[i] = __ldg(&W2[(i & 63) * 64 + (i >> 6)]);
    }
    // x -> half2 (coalesced grid-stride; 640K threads x 4 elements)
    const float2* x2 = (const float2*)x;
    int stride = gridDim.x * blockDim.x;
    for (int j = i; j < XH_N; j += stride) {
        float2 v = __ldg(&x2[j]);
        g_xh[j] = __floats2half2_rn(v.x, v.y);
    }
}

// K2: single-pass scan + scheduler ticket reset
__global__ void k_scan() {
    __shared__ int sc[256];
    __shared__ int sRed[8];
    int t = threadIdx.x;
    int bid = blockIdx.x;
    int lane = t & 31;
    int w = t >> 5;
    if (bid == 0 && t < 2) g_chunk2[t] = 0;

    int base = bid * 256;
    int s = 0;
    for (int j = t; j < base; j += 256) s += g_counts[j];
#pragma unroll
    for (int o = 16; o >= 1; o >>= 1) s += __shfl_xor_sync(0xffffffffu, s, o);
    if (lane == 0) sRed[w] = s;

    int i = base + t;
    int c = (i < V) ? g_counts[i] : 0;
    sc[t] = c;
    __syncthreads();
    int pref = sRed[0] + sRed[1] + sRed[2] + sRed[3] +
               sRed[4] + sRed[5] + sRed[6] + sRed[7];
    for (int o = 1; o < 256; o <<= 1) {
        int a = (t >= o) ? sc[t - o] : 0;
        __syncthreads();
        sc[t] += a;
        __syncthreads();
    }
    if (i < V) {
        int st = pref + sc[t] - c;   // global exclusive
        g_starts[i] = st;
        g_cursor[i] = st;
    }
}

// K4: scatter edges into CSR buckets — 1 edge/thread.
// Pack: (etype << 22) | src  ->  (e >> 16) == etype*64 == half2 rel offset.
__global__ void k_scatter(const int* __restrict__ ei) {
    int e = blockIdx.x * blockDim.x + threadIdx.x;
    if (e < E) {
        int src = ei[3 * e];
        int et  = ei[3 * e + 1];
        int dst = ei[3 * e + 2];
        int pos = atomicAdd(&g_cursor[dst], 1);
        g_edata[pos] = (et << 22) | src;
    }
}

// ---------------------------------------------------------------------------
// K5: fused aggregation + beta-residual + MLP + LayerNorm + skip.
// b-pair specialization (flavor = blockIdx&1), 4 blocks/SM, NV=16 chunks.
// fp16 on BOTH gather operands: x rows via half2 LDG (1 wf instead of 2) and
// relation via half2 LDS (R13 win). f32 accumulation; f32 self/residual.
// NOTE: gather-loop body is codegen-fragile (R8) — keep uniform __ldg bounds
// and self-term load after the edge loop.
__global__ __launch_bounds__(256, 4) void k_main(
    const float* __restrict__ x,
    const float* __restrict__ b1, const float* __restrict__ b2,
    const float* __restrict__ beta,
    const float* __restrict__ lnw, const float* __restrict__ lnb,
    float* __restrict__ out) {

    extern __shared__ float smem[];
    __half2* sRelH = (__half2*)smem;           // R*64 half2 = 16KB
    float* sH = smem + R * 64;                 // 128*SHST = 2560 floats (10KB)
    int*   sE = (int*)(sH + 128 * SHST);       // ECAP ints (6KB)
    __shared__ float sRS[NV][8];
    __shared__ float sRQ[NV][8];
    __shared__ int sChunk;

    int t = threadIdx.x;
    int w = t >> 5;
    int lane = t & 31;
    int flavor = blockIdx.x & 1;
    int bBase  = flavor << 1;

    // epilogue identity: 8 vertices per thread, octet selected by h
    int bb = t >> 7;           // local b (0/1)
    int h  = (t >> 6) & 1;     // vi octet (0: vi 0-7, 1: vi 8-15)
    int d  = t & 63;
    int b  = bBase + bb;

    // gather identity
    int gbl     = w & 1;       // local b
    int quarter = w >> 1;      // 0..3, 4 vertices each
    int gb      = bBase + gbl;

    // stage relation slice as fp16 (per lane d-pair)
    for (int i = t; i < R * 64; i += 256) {
        int r = i >> 6, c = i & 63;
        float2 rv = *(const float2*)&g_relation[(r << 8) + (bBase << 6) + 2 * c];
        sRelH[i] = __floats2half2_rn(rv.x, rv.y);
    }

    float bb1 = __ldg(b1 + d), bb2 = __ldg(b2 + d);
    float wln = __ldg(lnw + d), bln = __ldg(lnb + d);
    float2 bet2 = ((const float2*)beta)[lane];

    const __half2* xh  = g_xh + (size_t)gb * (V * 32) + lane;
    const float2*  xb2 = (const float2*)x + (size_t)gb * (V * D / 2) + lane;
    const float*   xres = x + (size_t)b * V * D + d;
    const __half2* sRelB = sRelH + (gbl << 5) + lane;

    for (;;) {
        if (t == 0) sChunk = atomicAdd(&g_chunk2[flavor], 1);
        __syncthreads();               // publishes sChunk; sE/sH safe to overwrite
        int chunk = sChunk;
        if (chunk >= NCHUNK) break;

        int v0 = chunk * NV;
        int eBeg = __ldg(&g_starts[v0]);
        int eEnd = (v0 + NV < V) ? __ldg(&g_starts[v0 + NV]) : E;
        int nE = eEnd - eBeg;

        int nStage = nE < ECAP ? nE : ECAP;
        for (int i = t; i < nStage; i += 256) sE[i] = __ldg(&g_edata[eBeg + i]);
        if (flavor == 0 && t < NV) g_counts[v0 + t] = 0;  // re-zero once
        __syncthreads();

        // ---- gather: each warp handles 4 vertices for its b ----
        for (int q = 0; q < 4; q++) {
            int vi = (quarter << 2) + q;
            int v  = v0 + vi;
            int lo  = __ldg(&g_starts[v]) - eBeg;
            int hi  = ((v + 1 < V) ? __ldg(&g_starts[v + 1]) : E) - eBeg;
            int cnt = hi - lo;
            float acc0 = 0.f, acc1 = 0.f;

            if (hi <= ECAP) {
                const int* ed = sE + lo;
                int j = 0;
                for (; j + 4 <= cnt; j += 4) {
                    int e0 = ed[j],     e1 = ed[j + 1];
                    int e2 = ed[j + 2], e3 = ed[j + 3];
                    float2 x0 = __half22float2(__ldg(xh + (e0 & 0x3FFFFF) * 32));
                    float2 x1 = __half22float2(__ldg(xh + (e1 & 0x3FFFFF) * 32));
                    float2 x2 = __half22float2(__ldg(xh + (e2 & 0x3FFFFF) * 32));
                    float2 x3 = __half22float2(__ldg(xh + (e3 & 0x3FFFFF) * 32));
                    float2 r0 = __half22float2(sRelB[e0 >> 16]);
                    float2 r1 = __half22float2(sRelB[e1 >> 16]);
                    float2 r2 = __half22float2(sRelB[e2 >> 16]);
                    float2 r3 = __half22float2(sRelB[e3 >> 16]);
                    acc0 = fmaf(r0.x, x0.x, acc0); acc1 = fmaf(r0.y, x0.y, acc1);
                    acc0 = fmaf(r1.x, x1.x, acc0); acc1 = fmaf(r1.y, x1.y, acc1);
                    acc0 = fmaf(r2.x, x2.x, acc0); acc1 = fmaf(r2.y, x2.y, acc1);
                    acc0 = fmaf(r3.x, x3.x, acc0); acc1 = fmaf(r3.y, x3.y, acc1);
                }
                for (; j < cnt; j++) {
                    int e = ed[j];
                    float2 xv = __half22float2(__ldg(xh + (e & 0x3FFFFF) * 32));
                    float2 rv = __half22float2(sRelB[e >> 16]);
                    acc0 = fmaf(rv.x, xv.x, acc0);
                    acc1 = fmaf(rv.y, xv.y, acc1);
                }
            } else {
                // rare fallback: chunk overflowed staging buffer
                const int* ed = g_edata + eBeg + lo;
                for (int j = 0; j < cnt; j++) {
                    int e = __ldg(ed + j);
                    float2 xv = __half22float2(__ldg(xh + (e & 0x3FFFFF) * 32));
                    float2 rv = __half22float2(sRelB[e >> 16]);
                    acc0 = fmaf(rv.x, xv.x, acc0);
                    acc1 = fmaf(rv.y, xv.y, acc1);
                }
            }

            float2 xs2 = __ldg(xb2 + (size_t)v * 32);   // f32 self term
            int base = ((gbl << 6) + 2 * lane) * SHST + vi;
            sH[base]        = fmaf(bet2.x, xs2.x, acc0);
            sH[base + SHST] = fmaf(bet2.y, xs2.y, acc1);
        }
        __syncthreads();

        // ---- matmul 1: s[j] = relu(h0[h*8+j] @ W1^T + b1) ----
        float s[8];
#pragma unroll
        for (int j = 0; j < 8; j++) s[j] = bb1;
#pragma unroll
        for (int k = 0; k < 64; k++) {
            float wv = __ldg(&g_W1T[(k << 6) + d]);
            const float4* hp = reinterpret_cast<const float4*>(&sH[((bb << 6) + k) * SHST]);
            float4 ha = hp[2 * h], hc = hp[2 * h + 1];
            s[0] = fmaf(ha.x, wv, s[0]); s[1] = fmaf(ha.y, wv, s[1]);
            s[2] = fmaf(ha.z, wv, s[2]); s[3] = fmaf(ha.w, wv, s[3]);
            s[4] = fmaf(hc.x, wv, s[4]); s[5] = fmaf(hc.y, wv, s[5]);
            s[6] = fmaf(hc.z, wv, s[6]); s[7] = fmaf(hc.w, wv, s[7]);
        }
        __syncthreads();
        {
            float4* sHrow = reinterpret_cast<float4*>(&sH[((bb << 6) + d) * SHST]);
            sHrow[2 * h]     = make_float4(fmaxf(s[0], 0.f), fmaxf(s[1], 0.f),
                                           fmaxf(s[2], 0.f), fmaxf(s[3], 0.f));
            sHrow[2 * h + 1] = make_float4(fmaxf(s[4], 0.f), fmaxf(s[5], 0.f),
                                           fmaxf(s[6], 0.f), fmaxf(s[7], 0.f));
        }
        __syncthreads();

        // ---- matmul 2: s[j] = t1[h*8+j] @ W2^T + b2 ----
#pragma unroll
        for (int j = 0; j < 8; j++) s[j] = bb2;
#pragma unroll
        for (int k = 0; k < 64; k++) {
            float wv = __ldg(&g_W2T[(k << 6) + d]);
            const float4* hp = reinterpret_cast<const float4*>(&sH[((bb << 6) + k) * SHST]);
            float4 ha = hp[2 * h], hc = hp[2 * h + 1];
            s[0] = fmaf(ha.x, wv, s[0]); s[1] = fmaf(ha.y, wv, s[1]);
            s[2] = fmaf(ha.z, wv, s[2]); s[3] = fmaf(ha.w, wv, s[3]);
            s[4] = fmaf(hc.x, wv, s[4]); s[5] = fmaf(hc.y, wv, s[5]);
            s[6] = fmaf(hc.z, wv, s[6]); s[7] = fmaf(hc.w, wv, s[7]);
        }

        // ---- LayerNorm (two-pass, warp shuffles + cross-warp combine) ----
        float mu[8];
#pragma unroll
        for (int j = 0; j < 8; j++) {
            float sm = s[j];
#pragma unroll
            for (int o = 16; o >= 1; o >>= 1)
                sm += __shfl_xor_sync(0xffffffffu, sm, o);
            if (lane == 0) sRS[(h << 3) + j][w] = sm;
        }
        __syncthreads();
#pragma unroll
        for (int j = 0; j < 8; j++)
            mu[j] = (sRS[(h << 3) + j][w] + sRS[(h << 3) + j][w ^ 1]) * (1.f / 64.f);
#pragma unroll
        for (int j = 0; j < 8; j++) {
            float hm = s[j] - mu[j];
            float q = hm * hm;
#pragma unroll
            for (int o = 16; o >= 1; o >>= 1)
                q += __shfl_xor_sync(0xffffffffu, q, o);
            if (lane == 0) sRQ[(h << 3) + j][w] = q;
        }
        __syncthreads();

        size_t obase = (size_t)b * V * D + (size_t)(v0 + (h << 3)) * D + d;
#pragma unroll
        for (int j = 0; j < 8; j++) {
            float var = (sRQ[(h << 3) + j][w] + sRQ[(h << 3) + j][w ^ 1]) * (1.f / 64.f);
            float hm  = s[j] - mu[j];
            float xself = __ldg(xres + (size_t)(v0 + (h << 3) + j) * D);
            out[obase + (size_t)j * D] =
                fmaf(hm * rsqrtf(var + LN_EPS), wln, bln) + xself;
        }
    }
}

// ---------------------------------------------------------------------------
extern "C" void kernel_launch(void* const* d_in, const int* in_sizes, int n_in,
                              void* d_out, int out_size) {
    const float* x    = (const float*)d_in[0];
    const float* z    = (const float*)d_in[1];
    const int*   ei   = (const int*)d_in[2];
    // d_in[3] = r_index (unused by the reference)
    const float* Wz   = (const float*)d_in[4];
    const float* bz   = (const float*)d_in[5];
    const float* W1   = (const float*)d_in[6];
    const float* b1   = (const float*)d_in[7];
    const float* W2   = (const float*)d_in[8];
    const float* b2   = (const float*)d_in[9];
    const float* beta = (const float*)d_in[10];
    const float* lnw  = (const float*)d_in[11];
    const float* lnb  = (const float*)d_in[12];
    float* out = (float*)d_out;

    const int SMEM_MAIN = R * 64 * 4 + 128 * SHST * 4 + ECAP * 4;  // 32640+... = 16K+10K+6K = 32768+... 
    cudaFuncSetAttribute(k_main, cudaFuncAttributeMaxDynamicSharedMemorySize,
                         SMEM_MAIN);

    k_hist_rel<<<(E + 255) / 256, 256>>>(ei, z, Wz, bz, W1, W2, x);
    k_scan<<<NBS, 256>>>();
    k_scatter<<<(E + 255) / 256, 256>>>(ei);
    k_main<<<GRID_MAIN, 256, SMEM_MAIN>>>(x, b1, b2, beta, lnw, lnb, out);
}